// round 14
// baseline (speedup 1.0000x reference)
#include <cuda_runtime.h>
#include <cuda_fp16.h>
#include <cstdint>

// ============================================================================
// GptOssMoEExperts: router collapses to identity (softmax over top-k sums to 1
// and the expert MLP is shared), so
//   out = ((x@Wg^T+bg) * silu(x@Wu^T+bu)) @ W2^T + b2
// R14 = R13 with the B-pointer off-by-one fixed: after the prologue loads B2,
// gBg/gBu must advance to tile 3 BEFORE the mainloop's first load_partB (which
// fills the tile-3 slot). R13 loaded tile-2 data into the tile-3 slot ->
// every B tile shifted one K-tile -> rel_err 1.4.
// GEMM1: CTA 128M x 64 out-cols, B tile = 128 rows (64 gate + 64 up of same
// cols), warps 2Mx2N, warp tile 64x64 (32 paired out cols): 8 ldsm / 32 MMAs,
// register-paired SiLU epilogue. Asymmetric rings (A 3-deep, B 4-deep, 112KB,
// 2 CTA/SM). Cross-kt B-fragment prefetch; A head frags post-barrier.
// GEMM2: proven config (CTA 128x96, warp 64x48, 4-stage).
// ============================================================================

#define SEQ   4096
#define HID   2880
#define INTER 2880
#define NGU   (2 * INTER)   // 5760

static constexpr int BM   = 128;
static constexpr int BK   = 64;              // fp16 elems -> 128B rows
static constexpr int KIT  = HID / BK;        // 45

// GEMM1 rings
static constexpr int TILE16K = 16384;                 // 128 rows x 128B
static constexpr int A_RING  = 3;
static constexpr int B_RING  = 4;
static constexpr uint32_t OFF_B1 = A_RING * TILE16K;  // 49152
static constexpr int SMEM1 = (A_RING + B_RING) * TILE16K;  // 114688 (112KB)

// GEMM2 (proven)
static constexpr int BN2    = 96;
static constexpr int STAGES2 = 4;
static constexpr int OFF_B2 = BM * 128;               // 16384
static constexpr int STAGE2 = OFF_B2 + BN2 * 128;     // 28672
static constexpr int SMEM2  = STAGES2 * STAGE2;       // 114688

// ---------------------------------------------------------------------------
// Scratch (__device__ globals = sanctioned allocation-free scratch)
// ---------------------------------------------------------------------------
__device__ __align__(128) __half g_xh [(size_t)SEQ * HID];
__device__ __align__(128) __half g_w1h[(size_t)NGU * HID];
__device__ __align__(128) __half g_w2h[(size_t)HID * INTER];
__device__ __align__(128) __half g_hh [(size_t)SEQ * INTER];

// ---------------------------------------------------------------------------
// PTX helpers
// ---------------------------------------------------------------------------
__device__ __forceinline__ uint32_t smem_u32(const void* p) {
    uint32_t a;
    asm("{ .reg .u64 t; cvta.to.shared.u64 t, %1; cvt.u32.u64 %0, t; }" : "=r"(a) : "l"(p));
    return a;
}
__device__ __forceinline__ void ldsm4(uint32_t* r, uint32_t a) {
    asm volatile("ldmatrix.sync.aligned.m8n8.x4.shared.b16 {%0,%1,%2,%3}, [%4];"
                 : "=r"(r[0]), "=r"(r[1]), "=r"(r[2]), "=r"(r[3]) : "r"(a));
}
__device__ __forceinline__ void mma16816(float* d, const uint32_t* a, const uint32_t* b) {
    asm volatile(
        "mma.sync.aligned.m16n8k16.row.col.f32.f16.f16.f32 "
        "{%0,%1,%2,%3}, {%4,%5,%6,%7}, {%8,%9}, {%0,%1,%2,%3};"
        : "+f"(d[0]), "+f"(d[1]), "+f"(d[2]), "+f"(d[3])
        : "r"(a[0]), "r"(a[1]), "r"(a[2]), "r"(a[3]), "r"(b[0]), "r"(b[1]));
}
__device__ __forceinline__ void cp16(uint32_t s, const void* g) {
    asm volatile("cp.async.cg.shared.global [%0], [%1], 16;" :: "r"(s), "l"(g) : "memory");
}
#define CP_COMMIT()  asm volatile("cp.async.commit_group;" ::: "memory")
#define CP_WAIT_1()  asm volatile("cp.async.wait_group 1;"  ::: "memory")

// ---------------------------------------------------------------------------
// fp32 -> fp16 conversion (vectorized)
// ---------------------------------------------------------------------------
__global__ void cvt_kernel(const float4* __restrict__ src, uint2* __restrict__ dst, int n4) {
    int i = blockIdx.x * blockDim.x + threadIdx.x;
    if (i >= n4) return;
    float4 v = src[i];
    __half2 a = __floats2half2_rn(v.x, v.y);
    __half2 b = __floats2half2_rn(v.z, v.w);
    uint2 o;
    o.x = *reinterpret_cast<uint32_t*>(&a);
    o.y = *reinterpret_cast<uint32_t*>(&b);
    dst[i] = o;
}

// ---------------------------------------------------------------------------
// GEMM1 (register-paired SiLU): h[:, nBase:nBase+64] =
//   (x@Wg^T+bg) * silu(x@Wu^T+bu)
// B smem tile rows 0-63 = W1 gate rows nBase.., rows 64-127 = W1 up rows
// INTER+nBase.. (same out cols). Warps 2Mx2N; warp (wm,wn): A rows wm*64..+64,
// B rows {wn*32..+32 gate, 64+wn*32..+32 up} = out cols wn*32..+32 paired.
// ---------------------------------------------------------------------------
__global__ void __launch_bounds__(128, 2)
gemm1_fused(const __half* __restrict__ A, const __half* __restrict__ W1,
            const float* __restrict__ b1, __half* __restrict__ h) {
    extern __shared__ __align__(128) char smem[];
    const uint32_t sb0 = smem_u32(smem);          // A ring base
    const uint32_t sbB = sb0 + OFF_B1;            // B ring base
    const int tid = threadIdx.x;
    const int l   = tid & 31;
    const int wid = tid >> 5;          // 0..3
    const int wm  = wid >> 1;          // 0..1
    const int wn  = wid & 1;           // 0..1
    const int mBase = blockIdx.x * BM;
    const int nBase = blockIdx.y * 64;

    // ---- strength-reduced cp.async addressing ----
    const int rowT = tid >> 3;                    // 0..15
    const int u8   = tid & 7;
    const uint32_t sOff = (uint32_t)rowT * 128 + (uint32_t)((u8 ^ (rowT & 7)) << 4);
    // Pointers track the NEXT tile to load for each operand.
    const __half* gA  = A  + (size_t)(mBase + rowT) * HID + u8 * 8;
    const __half* gBg = W1 + (size_t)(nBase + rowT) * HID + u8 * 8;          // gate
    const __half* gBu = W1 + (size_t)(INTER + nBase + rowT) * HID + u8 * 8;  // up

    // A: 8 chunks (128 rows); quarter p loads chunks 2p, 2p+1.
    auto load_partA = [&](uint32_t slotBase, int part) {
        #pragma unroll
        for (int k = 2 * part; k < 2 * part + 2; k++)
            cp16(slotBase + sOff + k * 2048, gA + (size_t)k * 16 * HID);
    };
    // B: 8 chunks (rows 0-63 gate = k 0..3, rows 64-127 up = k 4..7).
    auto load_partB = [&](uint32_t slotBase, int part) {
        #pragma unroll
        for (int k = 2 * part; k < 2 * part + 2; k++) {
            const __half* g = (k < 4) ? gBg + (size_t)k * 16 * HID
                                      : gBu + (size_t)(k - 4) * 16 * HID;
            cp16(slotBase + sOff + k * 2048, g);
        }
    };

    const int l7  = l & 7;
    const int lhi = l >> 4;
    const int le  = l & 15;
    const int q   = l >> 3;
    const int aRow0 = wm * 64 + le;
    const int bRowG = wn * 32 + ((q >> 1) << 3) + l7;        // gate rows
    const int bRowU = 64 + wn * 32 + ((q >> 1) << 3) + l7;   // up rows
    const int bUnit = q & 1;

    auto loadA = [&](uint32_t af[4][4], uint32_t sA, int ks) {
        #pragma unroll
        for (int i = 0; i < 4; i++)
            ldsm4(af[i], sA + (uint32_t)(aRow0 + i * 16) * 128 +
                           (uint32_t)(((ks * 2 + lhi) ^ l7) << 4));
    };
    auto loadB = [&](uint32_t bf[4][4], uint32_t sB, int ks) {
        const uint32_t un = (uint32_t)(((ks * 2 + bUnit) ^ l7) << 4);
        ldsm4(bf[0], sB + (uint32_t)(bRowG)      * 128 + un);
        ldsm4(bf[1], sB + (uint32_t)(bRowG + 16) * 128 + un);
        ldsm4(bf[2], sB + (uint32_t)(bRowU)      * 128 + un);
        ldsm4(bf[3], sB + (uint32_t)(bRowU + 16) * 128 + un);
    };

    float acc[4][8][4] = {};      // j 0-3 gate (32 cols), j 4-7 up (paired)
    uint32_t af[2][4][4], bf[2][4][4];

    // Prologue commits: P0={A0,B0}, P1={A1,B1}, P2={B2}.
    {
        #pragma unroll
        for (int p = 0; p < 4; p++) { load_partA(sb0, p);             load_partB(sbB, p); }
        CP_COMMIT();  gA += BK;  gBg += BK;  gBu += BK;
        #pragma unroll
        for (int p = 0; p < 4; p++) { load_partA(sb0 + TILE16K, p);   load_partB(sbB + TILE16K, p); }
        CP_COMMIT();  gA += BK;  gBg += BK;  gBu += BK;
        #pragma unroll
        for (int p = 0; p < 4; p++) load_partB(sbB + 2 * TILE16K, p);
        CP_COMMIT();
        gBg += BK;  gBu += BK;    // R14 FIX: B now points at tile 3 (next B to
                                  // load). R13 omitted this -> B shifted 1 tile.
        // gA points at tile 2 (next A to load) — A prologue loaded only 0,1.
    }

    CP_WAIT_1();                 // P0, P1 done: A0,A1,B0,B1 resident
    __syncthreads();
    loadA(af[0], sb0, 0);
    loadB(bf[0], sbB, 0);

    for (int kt = 0; kt < KIT; kt++) {
        const bool doA = (kt + 2) < KIT;
        const bool doB = (kt + 3) < KIT;
        const uint32_t aw = sb0 + ((kt + 2) % A_RING) * TILE16K;
        const uint32_t bw = sbB + ((kt + 3) % B_RING) * TILE16K;

        const uint32_t sA  = sb0 + (kt % A_RING) * TILE16K;
        const uint32_t sB  = sbB + (kt % B_RING) * TILE16K;
        const uint32_t sBn = sbB + ((kt + 1) % B_RING) * TILE16K;

        #pragma unroll
        for (int ks = 0; ks < 4; ks++) {
            const int cur = ks & 1, nxt = cur ^ 1;
            if (ks < 3) {
                loadA(af[nxt], sA, ks + 1);
                loadB(bf[nxt], sB, ks + 1);
            } else if (kt + 1 < KIT) {
                loadB(bf[nxt], sBn, 0);       // cross-kt B prefetch (resident)
            }
            if (doA) load_partA(aw, ks);
            if (doB) load_partB(bw, ks);
            #pragma unroll
            for (int i = 0; i < 4; i++)
                #pragma unroll
                for (int p = 0; p < 4; p++) {
                    mma16816(acc[i][2 * p],     af[cur][i], &bf[cur][p][0]);
                    mma16816(acc[i][2 * p + 1], af[cur][i], &bf[cur][p][2]);
                }
        }
        CP_COMMIT();                          // G_kt = {A_{kt+2}, B_{kt+3}}
        gA += BK;  gBg += BK;  gBu += BK;
        if (kt + 1 < KIT) {
            CP_WAIT_1();                      // done thru G_{kt-1}
            __syncthreads();
            loadA(af[0], sb0 + ((kt + 1) % A_RING) * TILE16K, 0);  // A head frags
        }
    }

    // ---- epilogue: register-paired SiLU, h fp16 ----
    const int r00 = mBase + wm * 64 + (l >> 2);
    const int cW  = nBase + wn * 32 + 2 * (l & 3);

    #pragma unroll
    for (int j = 0; j < 4; j++) {             // gate j pairs up j+4
        const int c = cW + j * 8;
        const float bg0 = __ldg(b1 + c);
        const float bg1 = __ldg(b1 + c + 1);
        const float bu0 = __ldg(b1 + INTER + c);
        const float bu1 = __ldg(b1 + INTER + c + 1);
        #pragma unroll
        for (int i = 0; i < 4; i++)
            #pragma unroll
            for (int hh = 0; hh < 2; hh++) {
                const int r = r00 + i * 16 + hh * 8;
                const float g0 = acc[i][j][2 * hh]         + bg0;
                const float g1 = acc[i][j][2 * hh + 1]     + bg1;
                const float u0 = acc[i][j + 4][2 * hh]     + bu0;
                const float u1 = acc[i][j + 4][2 * hh + 1] + bu1;
                const float h0 = g0 * u0 * (1.0f / (1.0f + __expf(-u0)));
                const float h1 = g1 * u1 * (1.0f / (1.0f + __expf(-u1)));
                *reinterpret_cast<__half2*>(h + (size_t)r * INTER + c) =
                    __floats2half2_rn(h0, h1);
            }
    }
}

// ---------------------------------------------------------------------------
// GEMM2: out = h @ W2^T + b2 (fp32). CTA 128x96, 4 warps (2Mx2N), warp 64x48.
// (proven config, unchanged)
// ---------------------------------------------------------------------------
__global__ void __launch_bounds__(128, 2)
gemm2(const __half* __restrict__ A, const __half* __restrict__ B,
      const float* __restrict__ bias, float* __restrict__ oF) {
    extern __shared__ __align__(128) char smem[];
    const uint32_t sb0 = smem_u32(smem);
    const int tid = threadIdx.x;
    const int l   = tid & 31;
    const int wid = tid >> 5;
    const int wm  = wid >> 1;
    const int wn  = wid & 1;
    const int mBase = blockIdx.x * BM;
    const int nBase = blockIdx.y * BN2;

    const int rowT = tid >> 3;
    const int u8   = tid & 7;
    const uint32_t aSmem = (uint32_t)rowT * 128 + (uint32_t)((u8 ^ (rowT & 7)) << 4);
    const uint32_t bSmem = OFF_B2 + aSmem;
    const __half* gAn = A + (size_t)(mBase + rowT) * HID + u8 * 8;
    const __half* gBn = B + (size_t)(nBase + rowT) * HID + u8 * 8;

    auto load_part = [&](uint32_t sbSlot, int part) {
        #pragma unroll
        for (int k = 2 * part; k < 2 * part + 2; k++)
            cp16(sbSlot + aSmem + k * 2048, gAn + (size_t)k * 16 * HID);
        if (part < 2) {
            #pragma unroll
            for (int k = 2 * part; k < 2 * part + 2; k++)
                cp16(sbSlot + bSmem + k * 2048, gBn + (size_t)k * 16 * HID);
        } else {
            const int k = part + 2;
            cp16(sbSlot + bSmem + k * 2048, gBn + (size_t)k * 16 * HID);
        }
    };

    const int l7  = l & 7;
    const int lhi = l >> 4;
    const int le  = l & 15;
    const int q   = l >> 3;
    const int aRow0 = wm * 64 + le;
    const int bRowO = wn * 48 + ((q >> 1) << 3) + l7;
    const int bUnit = q & 1;

    auto loadA = [&](uint32_t af[4][4], uint32_t sA, int ks) {
        #pragma unroll
        for (int i = 0; i < 4; i++)
            ldsm4(af[i], sA + (uint32_t)(aRow0 + i * 16) * 128 +
                           (uint32_t)(((ks * 2 + lhi) ^ l7) << 4));
    };
    auto loadB = [&](uint32_t bf[3][4], uint32_t sB, int ks) {
        #pragma unroll
        for (int p = 0; p < 3; p++)
            ldsm4(bf[p], sB + (uint32_t)(bRowO + p * 16) * 128 +
                           (uint32_t)(((ks * 2 + bUnit) ^ l7) << 4));
    };

    float acc[4][6][4] = {};
    uint32_t af[2][4][4], bf[2][3][4];

    #pragma unroll
    for (int s = 0; s < STAGES2 - 1; s++) {
        const uint32_t sbSlot = sb0 + s * STAGE2;
        #pragma unroll
        for (int p = 0; p < 4; p++) load_part(sbSlot, p);
        CP_COMMIT();
        gAn += BK;  gBn += BK;
    }

    CP_WAIT_1();
    __syncthreads();
    loadA(af[0], sb0, 0);
    loadB(bf[0], sb0 + OFF_B2, 0);

    for (int kt = 0; kt < KIT; kt++) {
        const int  nk     = kt + STAGES2 - 1;
        const bool doLoad = nk < KIT;
        const uint32_t sbSlot = sb0 + (nk % STAGES2) * STAGE2;

        const uint32_t sA  = sb0 + (kt % STAGES2) * STAGE2;
        const uint32_t sB  = sA + OFF_B2;
        const uint32_t sAn = sb0 + ((kt + 1) % STAGES2) * STAGE2;
        const uint32_t sBn = sAn + OFF_B2;

        #pragma unroll
        for (int ks = 0; ks < 4; ks++) {
            const int cur = ks & 1, nxt = cur ^ 1;
            if (ks < 3) {
                loadA(af[nxt], sA, ks + 1);
                loadB(bf[nxt], sB, ks + 1);
            } else if (kt + 1 < KIT) {
                loadA(af[nxt], sAn, 0);
                loadB(bf[nxt], sBn, 0);
            }
            if (doLoad) load_part(sbSlot, ks);
            #pragma unroll
            for (int i = 0; i < 4; i++)
                #pragma unroll
                for (int p = 0; p < 3; p++) {
                    mma16816(acc[i][2 * p],     af[cur][i], &bf[cur][p][0]);
                    mma16816(acc[i][2 * p + 1], af[cur][i], &bf[cur][p][2]);
                }
        }
        CP_COMMIT();
        gAn += BK;  gBn += BK;
        if (kt + 1 < KIT) {
            CP_WAIT_1();
            __syncthreads();
        }
    }

    const int r00 = mBase + wm * 64 + (l >> 2);
    const int cB  = nBase + wn * 48 + 2 * (l & 3);

    #pragma unroll
    for (int i = 0; i < 4; i++)
        #pragma unroll
        for (int j = 0; j < 6; j++) {
            const int c = cB + j * 8;
            const float b0 = __ldg(bias + c), b1v = __ldg(bias + c + 1);
            #pragma unroll
            for (int hh = 0; hh < 2; hh++) {
                const int r = r00 + i * 16 + hh * 8;
                *reinterpret_cast<float2*>(oF + (size_t)r * HID + c) =
                    make_float2(acc[i][j][2 * hh] + b0,
                                acc[i][j][2 * hh + 1] + b1v);
            }
        }
}

// ---------------------------------------------------------------------------
// Host
// ---------------------------------------------------------------------------
extern "C" void kernel_launch(void* const* d_in, const int* in_sizes, int n_in,
                              void* d_out, int out_size) {
    const float* x  = (const float*)d_in[0];   // hidden_states (4096, 2880)
    const float* w1 = (const float*)d_in[3];   // gate_up_w (5760, 2880)
    const float* b1 = (const float*)d_in[4];   // gate_up_b (5760,)
    const float* w2 = (const float*)d_in[5];   // down_w (2880, 2880)
    const float* b2 = (const float*)d_in[6];   // down_b (2880,)
    float* out = (float*)d_out;                // (4096, 2880) fp32

    void *px, *pw1, *pw2, *ph;
    cudaGetSymbolAddress(&px,  g_xh);
    cudaGetSymbolAddress(&pw1, g_w1h);
    cudaGetSymbolAddress(&pw2, g_w2h);
    cudaGetSymbolAddress(&ph,  g_hh);

    // fp32 -> fp16
    {
        int n4 = (SEQ * HID) / 4;
        cvt_kernel<<<(n4 + 255) / 256, 256>>>((const float4*)x,  (uint2*)px,  n4);
        n4 = (NGU * HID) / 4;
        cvt_kernel<<<(n4 + 255) / 256, 256>>>((const float4*)w1, (uint2*)pw1, n4);
        n4 = (HID * INTER) / 4;
        cvt_kernel<<<(n4 + 255) / 256, 256>>>((const float4*)w2, (uint2*)pw2, n4);
    }

    cudaFuncSetAttribute(gemm1_fused,
                         cudaFuncAttributeMaxDynamicSharedMemorySize, SMEM1);
    cudaFuncSetAttribute(gemm2,
                         cudaFuncAttributeMaxDynamicSharedMemorySize, SMEM2);

    // GEMM1 fused: h = (x@Wg^T+bg) * silu(x@Wu^T+bu)   (fp16, 4096 x 2880)
    gemm1_fused<<<dim3(SEQ / BM, INTER / 64), 128, SMEM1>>>(
        (const __half*)px, (const __half*)pw1, b1, (__half*)ph);

    // GEMM2: out = h @ W2^T + b2   (fp32, 4096 x 2880)
    gemm2<<<dim3(SEQ / BM, HID / BN2), 128, SMEM2>>>(
        (const __half*)ph, (const __half*)pw2, b2, out);
}

// round 15
// speedup vs baseline: 1.0779x; 1.0779x over previous
#include <cuda_runtime.h>
#include <cuda_fp16.h>
#include <cstdint>

// ============================================================================
// GptOssMoEExperts: router collapses to identity (softmax over top-k sums to 1
// and the expert MLP is shared), so
//   out = ((x@Wg^T+bg) * silu(x@Wu^T+bu)) @ W2^T + b2
// R15: GEMM1 = R12 exactly (best: 32x96-paired SiLU fusion, 199 regs, 4-stage,
// cross-kt prefetch). GEMM2 = NEW BN=160 (grid 576 -> 2 waves @0.973 vs 4
// waves @0.81), warp 64x80 (9 ldsm / 40 MMAs), 3-stage R8-style loop.
// cvt: single merged launch for all three fp32->fp16 conversions.
// ============================================================================

#define SEQ   4096
#define HID   2880
#define INTER 2880
#define NGU   (2 * INTER)   // 5760

static constexpr int BM   = 128;
static constexpr int BK   = 64;              // fp16 elems -> 128B rows
static constexpr int KIT  = HID / BK;        // 45

// GEMM1 (R12)
static constexpr int BN1     = 96;                    // 48 gate + 48 up rows
static constexpr int STAGES1 = 4;
static constexpr int OFF_B1  = BM * 128;              // 16384
static constexpr int STAGE1  = OFF_B1 + BN1 * 128;    // 28672
static constexpr int SMEM1   = STAGES1 * STAGE1;      // 114688

// GEMM2 (new BN=160)
static constexpr int BN2     = 160;
static constexpr int STAGES2 = 3;
static constexpr int OFF_B2  = BM * 128;              // 16384
static constexpr int STAGE2  = OFF_B2 + BN2 * 128;    // 36864
static constexpr int SMEM2   = STAGES2 * STAGE2;      // 110592 (x2 = 216KB/SM)

// ---------------------------------------------------------------------------
// Scratch (__device__ globals = sanctioned allocation-free scratch)
// ---------------------------------------------------------------------------
__device__ __align__(128) __half g_xh [(size_t)SEQ * HID];
__device__ __align__(128) __half g_w1h[(size_t)NGU * HID];
__device__ __align__(128) __half g_w2h[(size_t)HID * INTER];
__device__ __align__(128) __half g_hh [(size_t)SEQ * INTER];

// ---------------------------------------------------------------------------
// PTX helpers
// ---------------------------------------------------------------------------
__device__ __forceinline__ uint32_t smem_u32(const void* p) {
    uint32_t a;
    asm("{ .reg .u64 t; cvta.to.shared.u64 t, %1; cvt.u32.u64 %0, t; }" : "=r"(a) : "l"(p));
    return a;
}
__device__ __forceinline__ void ldsm4(uint32_t* r, uint32_t a) {
    asm volatile("ldmatrix.sync.aligned.m8n8.x4.shared.b16 {%0,%1,%2,%3}, [%4];"
                 : "=r"(r[0]), "=r"(r[1]), "=r"(r[2]), "=r"(r[3]) : "r"(a));
}
__device__ __forceinline__ void mma16816(float* d, const uint32_t* a, const uint32_t* b) {
    asm volatile(
        "mma.sync.aligned.m16n8k16.row.col.f32.f16.f16.f32 "
        "{%0,%1,%2,%3}, {%4,%5,%6,%7}, {%8,%9}, {%0,%1,%2,%3};"
        : "+f"(d[0]), "+f"(d[1]), "+f"(d[2]), "+f"(d[3])
        : "r"(a[0]), "r"(a[1]), "r"(a[2]), "r"(a[3]), "r"(b[0]), "r"(b[1]));
}
__device__ __forceinline__ void cp16(uint32_t s, const void* g) {
    asm volatile("cp.async.cg.shared.global [%0], [%1], 16;" :: "r"(s), "l"(g) : "memory");
}
#define CP_COMMIT()  asm volatile("cp.async.commit_group;" ::: "memory")
#define CP_WAIT_1()  asm volatile("cp.async.wait_group 1;"  ::: "memory")

// ---------------------------------------------------------------------------
// Merged fp32 -> fp16 conversion for all three inputs (one launch)
// ---------------------------------------------------------------------------
__global__ void cvt3_kernel(const float4* __restrict__ s0, uint2* __restrict__ d0, int n0,
                            const float4* __restrict__ s1, uint2* __restrict__ d1, int n1,
                            const float4* __restrict__ s2, uint2* __restrict__ d2, int n2) {
    int i = blockIdx.x * blockDim.x + threadIdx.x;
    const float4* s;  uint2* d;  int j;
    if (i < n0)            { s = s0; d = d0; j = i; }
    else if (i < n0 + n1)  { s = s1; d = d1; j = i - n0; }
    else if (i < n0 + n1 + n2) { s = s2; d = d2; j = i - n0 - n1; }
    else return;
    float4 v = s[j];
    __half2 a = __floats2half2_rn(v.x, v.y);
    __half2 b = __floats2half2_rn(v.z, v.w);
    uint2 o;
    o.x = *reinterpret_cast<uint32_t*>(&a);
    o.y = *reinterpret_cast<uint32_t*>(&b);
    d[j] = o;
}

// ---------------------------------------------------------------------------
// GEMM1 (R12, register-paired SiLU fusion): CTA computes 48 output cols.
// B tile rows 0-47 = W1 gate rows, rows 48-95 = W1 up rows (same cols).
// 4 M-warps, warp tile 32x96: acc[i][j] gate pairs acc[i][j+6] up in-thread.
// 4-stage cp.async, cross-kt fragment prefetch, interleaved LDGSTS quarters.
// ---------------------------------------------------------------------------
__global__ void __launch_bounds__(128, 2)
gemm1_fused(const __half* __restrict__ A, const __half* __restrict__ W1,
            const float* __restrict__ b1, __half* __restrict__ h) {
    extern __shared__ __align__(128) char smem[];
    const uint32_t sb0 = smem_u32(smem);
    const int tid = threadIdx.x;
    const int l   = tid & 31;
    const int wm  = tid >> 5;          // 0..3 (all M-warps)
    const int mBase = blockIdx.x * BM;
    const int nBase = blockIdx.y * 48;

    const int rowT = tid >> 3;
    const int u8   = tid & 7;
    const uint32_t aSmem = (uint32_t)rowT * 128 + (uint32_t)((u8 ^ (rowT & 7)) << 4);
    const uint32_t bSmem = OFF_B1 + aSmem;
    const __half* gAn = A  + (size_t)(mBase + rowT) * HID + u8 * 8;
    const __half* gBg = W1 + (size_t)(nBase + rowT) * HID + u8 * 8;
    const __half* gBu = W1 + (size_t)(INTER + nBase + rowT) * HID + u8 * 8;

    auto bptr = [&](int k) -> const __half* {
        return (k < 3) ? gBg + (size_t)k * 16 * HID
                       : gBu + (size_t)(k - 3) * 16 * HID;
    };
    auto load_part = [&](uint32_t sbSlot, int part) {
        #pragma unroll
        for (int k = 2 * part; k < 2 * part + 2; k++)
            cp16(sbSlot + aSmem + k * 2048, gAn + (size_t)k * 16 * HID);
        if (part < 2) {
            #pragma unroll
            for (int k = 2 * part; k < 2 * part + 2; k++)
                cp16(sbSlot + bSmem + k * 2048, bptr(k));
        } else {
            const int k = part + 2;
            cp16(sbSlot + bSmem + k * 2048, bptr(k));
        }
    };

    const int l7  = l & 7;
    const int lhi = l >> 4;
    const int le  = l & 15;
    const int q   = l >> 3;
    const int aRow0 = wm * 32 + le;
    const int bRowO = ((q >> 1) << 3) + l7;
    const int bUnit = q & 1;

    auto loadA = [&](uint32_t af[2][4], uint32_t sA, int ks) {
        #pragma unroll
        for (int i = 0; i < 2; i++)
            ldsm4(af[i], sA + (uint32_t)(aRow0 + i * 16) * 128 +
                           (uint32_t)(((ks * 2 + lhi) ^ l7) << 4));
    };
    auto loadB = [&](uint32_t bf[6][4], uint32_t sB, int ks) {
        #pragma unroll
        for (int p = 0; p < 6; p++)
            ldsm4(bf[p], sB + (uint32_t)(bRowO + p * 16) * 128 +
                           (uint32_t)(((ks * 2 + bUnit) ^ l7) << 4));
    };

    float acc[2][12][4] = {};
    uint32_t af[2][2][4], bf[2][6][4];

    #pragma unroll
    for (int s = 0; s < STAGES1 - 1; s++) {
        const uint32_t sbSlot = sb0 + s * STAGE1;
        #pragma unroll
        for (int p = 0; p < 4; p++) load_part(sbSlot, p);
        CP_COMMIT();
        gAn += BK;  gBg += BK;  gBu += BK;
    }

    CP_WAIT_1();
    __syncthreads();
    loadA(af[0], sb0, 0);
    loadB(bf[0], sb0 + OFF_B1, 0);

    for (int kt = 0; kt < KIT; kt++) {
        const int  nk     = kt + STAGES1 - 1;
        const bool doLoad = nk < KIT;
        const uint32_t sbSlot = sb0 + (nk % STAGES1) * STAGE1;

        const uint32_t sA  = sb0 + (kt % STAGES1) * STAGE1;
        const uint32_t sB  = sA + OFF_B1;
        const uint32_t sAn = sb0 + ((kt + 1) % STAGES1) * STAGE1;
        const uint32_t sBn = sAn + OFF_B1;

        #pragma unroll
        for (int ks = 0; ks < 4; ks++) {
            const int cur = ks & 1, nxt = cur ^ 1;
            if (ks < 3) {
                loadA(af[nxt], sA, ks + 1);
                loadB(bf[nxt], sB, ks + 1);
            } else if (kt + 1 < KIT) {
                loadA(af[nxt], sAn, 0);       // cross-kt prefetch
                loadB(bf[nxt], sBn, 0);
            }
            if (doLoad) load_part(sbSlot, ks);
            #pragma unroll
            for (int i = 0; i < 2; i++)
                #pragma unroll
                for (int p = 0; p < 6; p++) {
                    mma16816(acc[i][2 * p],     af[cur][i], &bf[cur][p][0]);
                    mma16816(acc[i][2 * p + 1], af[cur][i], &bf[cur][p][2]);
                }
        }
        CP_COMMIT();
        gAn += BK;  gBg += BK;  gBu += BK;
        if (kt + 1 < KIT) {
            CP_WAIT_1();
            __syncthreads();
        }
    }

    // ---- epilogue: register-paired SiLU, h fp16 ----
    const int r00 = mBase + wm * 32 + (l >> 2);
    const int cL  = 2 * (l & 3);

    #pragma unroll
    for (int j = 0; j < 6; j++) {                 // gate j pairs up j+6
        const int c = cL + j * 8;
        const float bg0 = __ldg(b1 + nBase + c);
        const float bg1 = __ldg(b1 + nBase + c + 1);
        const float bu0 = __ldg(b1 + INTER + nBase + c);
        const float bu1 = __ldg(b1 + INTER + nBase + c + 1);
        #pragma unroll
        for (int i = 0; i < 2; i++)
            #pragma unroll
            for (int hh = 0; hh < 2; hh++) {
                const int r = r00 + i * 16 + hh * 8;
                const float g0 = acc[i][j][2 * hh]         + bg0;
                const float g1 = acc[i][j][2 * hh + 1]     + bg1;
                const float u0 = acc[i][j + 6][2 * hh]     + bu0;
                const float u1 = acc[i][j + 6][2 * hh + 1] + bu1;
                const float h0 = g0 * u0 * (1.0f / (1.0f + __expf(-u0)));
                const float h1 = g1 * u1 * (1.0f / (1.0f + __expf(-u1)));
                *reinterpret_cast<__half2*>(
                    h + (size_t)r * INTER + nBase + c) =
                    __floats2half2_rn(h0, h1);
            }
    }
}

// ---------------------------------------------------------------------------
// GEMM2: out = h @ W2^T + b2 (fp32). CTA 128x160, 4 warps (2Mx2N),
// warp tile 64x80 (9 ldsm / 40 MMAs). 3-stage cp.async, R8-style loop
// (no cross-kt prefetch; interleaved LDGSTS quarters). Grid 576 -> 2 waves.
// ---------------------------------------------------------------------------
__global__ void __launch_bounds__(128, 2)
gemm2(const __half* __restrict__ A, const __half* __restrict__ B,
      const float* __restrict__ bias, float* __restrict__ oF) {
    extern __shared__ __align__(128) char smem[];
    const uint32_t sb0 = smem_u32(smem);
    const int tid = threadIdx.x;
    const int l   = tid & 31;
    const int wid = tid >> 5;
    const int wm  = wid >> 1;
    const int wn  = wid & 1;
    const int mBase = blockIdx.x * BM;
    const int nBase = blockIdx.y * BN2;

    const int rowT = tid >> 3;
    const int u8   = tid & 7;
    const uint32_t aSmem = (uint32_t)rowT * 128 + (uint32_t)((u8 ^ (rowT & 7)) << 4);
    const uint32_t bSmem = OFF_B2 + aSmem;
    const __half* gAn = A + (size_t)(mBase + rowT) * HID + u8 * 8;
    const __half* gBn = B + (size_t)(nBase + rowT) * HID + u8 * 8;

    // Per stage per thread: A 8 chunks, B 10 chunks (160 rows).
    // Quarters: p0 A{0,1}+B{0,1,2}; p1 A{2,3}+B{3,4,5}; p2 A{4,5}+B{6,7};
    //           p3 A{6,7}+B{8,9}.
    auto load_part = [&](uint32_t sbSlot, int part) {
        #pragma unroll
        for (int k = 2 * part; k < 2 * part + 2; k++)
            cp16(sbSlot + aSmem + k * 2048, gAn + (size_t)k * 16 * HID);
        const int b0 = (part < 2) ? 3 * part : (6 + 2 * (part - 2));
        const int nb = (part < 2) ? 3 : 2;
        #pragma unroll
        for (int k = b0; k < b0 + nb; k++)
            cp16(sbSlot + bSmem + k * 2048, gBn + (size_t)k * 16 * HID);
    };

    const int l7  = l & 7;
    const int lhi = l >> 4;
    const int le  = l & 15;
    const int q   = l >> 3;
    const int aRow0 = wm * 64 + le;
    const int bRowO = wn * 80 + ((q >> 1) << 3) + l7;
    const int bUnit = q & 1;

    auto loadA = [&](uint32_t af[4][4], uint32_t sA, int ks) {
        #pragma unroll
        for (int i = 0; i < 4; i++)
            ldsm4(af[i], sA + (uint32_t)(aRow0 + i * 16) * 128 +
                           (uint32_t)(((ks * 2 + lhi) ^ l7) << 4));
    };
    auto loadB = [&](uint32_t bf[5][4], uint32_t sB, int ks) {
        #pragma unroll
        for (int p = 0; p < 5; p++)
            ldsm4(bf[p], sB + (uint32_t)(bRowO + p * 16) * 128 +
                           (uint32_t)(((ks * 2 + bUnit) ^ l7) << 4));
    };

    float acc[4][10][4] = {};
    uint32_t af[2][4][4], bf[2][5][4];

    #pragma unroll
    for (int s = 0; s < STAGES2 - 1; s++) {               // prologue: 2 stages
        const uint32_t sbSlot = sb0 + s * STAGE2;
        #pragma unroll
        for (int p = 0; p < 4; p++) load_part(sbSlot, p);
        CP_COMMIT();
        gAn += BK;  gBn += BK;
    }

    for (int kt = 0; kt < KIT; kt++) {
        CP_WAIT_1();          // stage kt resident
        __syncthreads();

        const int  nk     = kt + STAGES2 - 1;
        const bool doLoad = nk < KIT;
        const uint32_t sbSlot = sb0 + (nk % STAGES2) * STAGE2;

        const uint32_t sA = sb0 + (kt % STAGES2) * STAGE2;
        const uint32_t sB = sA + OFF_B2;

        loadA(af[0], sA, 0);
        loadB(bf[0], sB, 0);
        #pragma unroll
        for (int ks = 0; ks < 4; ks++) {
            const int cur = ks & 1, nxt = cur ^ 1;
            if (ks < 3) {
                loadA(af[nxt], sA, ks + 1);
                loadB(bf[nxt], sB, ks + 1);
            }
            if (doLoad) load_part(sbSlot, ks);
            #pragma unroll
            for (int i = 0; i < 4; i++)
                #pragma unroll
                for (int p = 0; p < 5; p++) {
                    mma16816(acc[i][2 * p],     af[cur][i], &bf[cur][p][0]);
                    mma16816(acc[i][2 * p + 1], af[cur][i], &bf[cur][p][2]);
                }
        }
        CP_COMMIT();
        gAn += BK;  gBn += BK;
    }

    // ------------------------------- epilogue -------------------------------
    const int r00 = mBase + wm * 64 + (l >> 2);
    const int cB  = nBase + wn * 80 + 2 * (l & 3);

    #pragma unroll
    for (int i = 0; i < 4; i++)
        #pragma unroll
        for (int j = 0; j < 10; j++) {
            const int c = cB + j * 8;
            const float b0 = __ldg(bias + c), b1v = __ldg(bias + c + 1);
            #pragma unroll
            for (int hh = 0; hh < 2; hh++) {
                const int r = r00 + i * 16 + hh * 8;
                *reinterpret_cast<float2*>(oF + (size_t)r * HID + c) =
                    make_float2(acc[i][j][2 * hh] + b0,
                                acc[i][j][2 * hh + 1] + b1v);
            }
        }
}

// ---------------------------------------------------------------------------
// Host
// ---------------------------------------------------------------------------
extern "C" void kernel_launch(void* const* d_in, const int* in_sizes, int n_in,
                              void* d_out, int out_size) {
    const float* x  = (const float*)d_in[0];   // hidden_states (4096, 2880)
    const float* w1 = (const float*)d_in[3];   // gate_up_w (5760, 2880)
    const float* b1 = (const float*)d_in[4];   // gate_up_b (5760,)
    const float* w2 = (const float*)d_in[5];   // down_w (2880, 2880)
    const float* b2 = (const float*)d_in[6];   // down_b (2880,)
    float* out = (float*)d_out;                // (4096, 2880) fp32

    void *px, *pw1, *pw2, *ph;
    cudaGetSymbolAddress(&px,  g_xh);
    cudaGetSymbolAddress(&pw1, g_w1h);
    cudaGetSymbolAddress(&pw2, g_w2h);
    cudaGetSymbolAddress(&ph,  g_hh);

    // fp32 -> fp16: single merged launch
    {
        const int n0 = (SEQ * HID) / 4;
        const int n1 = (NGU * HID) / 4;
        const int n2 = (HID * INTER) / 4;
        const int nt = n0 + n1 + n2;
        cvt3_kernel<<<(nt + 255) / 256, 256>>>(
            (const float4*)x,  (uint2*)px,  n0,
            (const float4*)w1, (uint2*)pw1, n1,
            (const float4*)w2, (uint2*)pw2, n2);
    }

    cudaFuncSetAttribute(gemm1_fused,
                         cudaFuncAttributeMaxDynamicSharedMemorySize, SMEM1);
    cudaFuncSetAttribute(gemm2,
                         cudaFuncAttributeMaxDynamicSharedMemorySize, SMEM2);

    // GEMM1 fused: h = (x@Wg^T+bg) * silu(x@Wu^T+bu)   (fp16, 4096 x 2880)
    gemm1_fused<<<dim3(SEQ / BM, INTER / 48), 128, SMEM1>>>(
        (const __half*)px, (const __half*)pw1, b1, (__half*)ph);

    // GEMM2: out = h @ W2^T + b2   (fp32, 4096 x 2880)
    gemm2<<<dim3(SEQ / BM, HID / BN2), 128, SMEM2>>>(
        (const __half*)ph, (const __half*)pw2, b2, out);
}